// round 2
// baseline (speedup 1.0000x reference)
#include <cuda_runtime.h>

#define NN 30000
#define NE 480000
#define ND 128       // NODE_DIM
#define SPH 480
#define HID 576
#define NIR 224
#define NB 20
#define EB 4         // edges per barrier batch

// ---------------- scratch (allocation-free: device globals) ----------------
__device__ float g_h[NN * ND];     // silu(x@W1+b1)
__device__ float g_so[NN * HID];   // scalar_out

// ---------------- packed fp32x2 FMA (Blackwell FFMA2) ----------------
__device__ __forceinline__ float2 ffma2(float2 a, float2 b, float2 c) {
    unsigned long long ua = *(unsigned long long*)&a;
    unsigned long long ub = *(unsigned long long*)&b;
    unsigned long long uc = *(unsigned long long*)&c;
    unsigned long long ud;
    asm("fma.rn.f32x2 %0, %1, %2, %3;" : "=l"(ud) : "l"(ua), "l"(ub), "l"(uc));
    return *(float2*)&ud;
}

// ---------------- vectorized L2 reduction ----------------
__device__ __forceinline__ void red4(float* addr, float4 v) {
    asm volatile("red.global.add.v4.f32 [%0], {%1, %2, %3, %4};"
                 :: "l"(addr), "f"(v.x), "f"(v.y), "f"(v.z), "f"(v.w)
                 : "memory");
}

// ---------------- out init: new = x (+ scatter adds later) ----------------
__global__ void init_out_kernel(const float* __restrict__ xs,
                                const float* __restrict__ xsph,
                                float* __restrict__ out) {
    const int n1 = NN * ND / 4;
    const int nt = n1 + NN * SPH / 4;
    const float4* a = (const float4*)xs;
    const float4* b = (const float4*)xsph;
    float4* o = (float4*)out;
    for (int i = blockIdx.x * blockDim.x + threadIdx.x; i < nt;
         i += gridDim.x * blockDim.x) {
        o[i] = (i < n1) ? a[i] : b[i - n1];
    }
}

// ---------------- generic K=128 GEMM: C = act(A[Mx128] @ B[128xN] + bias) ----
template <int N, bool SILU>
__global__ void gemm_k128(const float* __restrict__ A,
                          const float* __restrict__ B,
                          const float* __restrict__ bias,
                          float* __restrict__ C, int M) {
    extern __shared__ float sm[];
    float* As = sm;              // [128][68] A^T (k-major), padded
    float* Bs = sm + 128 * 68;   // [128][64]

    const int row0 = blockIdx.x * 64;
    const int tid = threadIdx.x;

    for (int i = tid; i < 64 * 128; i += 256) {
        int r = i >> 7, k = i & 127;
        float v = (row0 + r < M) ? A[(row0 + r) * ND + k] : 0.f;
        As[k * 68 + r] = v;
    }

    const int tr = tid & 15;
    const int tc = tid >> 4;

    for (int ct = 0; ct < N / 64; ct++) {
        __syncthreads();
        for (int i = tid; i < 128 * 64; i += 256) {
            int k = i >> 6, c = i & 63;
            Bs[k * 64 + c] = B[k * N + ct * 64 + c];
        }
        __syncthreads();

        float acc[4][4] = {};
#pragma unroll 8
        for (int k = 0; k < 128; k++) {
            float4 a = *(const float4*)&As[k * 68 + tr * 4];
            float4 b = *(const float4*)&Bs[k * 64 + tc * 4];
            acc[0][0] = fmaf(a.x, b.x, acc[0][0]);
            acc[0][1] = fmaf(a.x, b.y, acc[0][1]);
            acc[0][2] = fmaf(a.x, b.z, acc[0][2]);
            acc[0][3] = fmaf(a.x, b.w, acc[0][3]);
            acc[1][0] = fmaf(a.y, b.x, acc[1][0]);
            acc[1][1] = fmaf(a.y, b.y, acc[1][1]);
            acc[1][2] = fmaf(a.y, b.z, acc[1][2]);
            acc[1][3] = fmaf(a.y, b.w, acc[1][3]);
            acc[2][0] = fmaf(a.z, b.x, acc[2][0]);
            acc[2][1] = fmaf(a.z, b.y, acc[2][1]);
            acc[2][2] = fmaf(a.z, b.z, acc[2][2]);
            acc[2][3] = fmaf(a.z, b.w, acc[2][3]);
            acc[3][0] = fmaf(a.w, b.x, acc[3][0]);
            acc[3][1] = fmaf(a.w, b.y, acc[3][1]);
            acc[3][2] = fmaf(a.w, b.z, acc[3][2]);
            acc[3][3] = fmaf(a.w, b.w, acc[3][3]);
        }

#pragma unroll
        for (int i = 0; i < 4; i++) {
            int r = row0 + tr * 4 + i;
            if (r < M) {
#pragma unroll
                for (int j = 0; j < 4; j++) {
                    int c = ct * 64 + tc * 4 + j;
                    float v = acc[i][j] + bias[c];
                    if (SILU) v = v / (1.f + __expf(-v));
                    C[r * N + c] = v;
                }
            }
        }
    }
}

// ---------------- edge kernel v2 ----------------
// 96 threads/block. Each thread owns 3 column-PAIRS of HID=576 (cols 2p, 2p+1
// with p = t + 96k), Wrbf held packed in registers (120 regs). EB=4 edges per
// barrier batch; FFMA2 for the 20-deep matvec; vectorized red4 scatter.
__global__ void __launch_bounds__(96, 3) edge_kernel(
    const float* __restrict__ xsph, const float* __restrict__ rbf,
    const float* __restrict__ fcut, const float* __restrict__ rsh,
    const int* __restrict__ eidx, const float* __restrict__ Wrbf,
    const float* __restrict__ brbf, float* __restrict__ out) {
    const int t = threadIdx.x;

    // persistent packed weights: 3 pairs x 20 basis
    float2 w2[3][NB];
    float2 bb2[3];
#pragma unroll
    for (int k = 0; k < 3; k++) {
        int c = 2 * (t + 96 * k);
        bb2[k] = *(const float2*)&brbf[c];
#pragma unroll
        for (int b = 0; b < NB; b++)
            w2[k][b] = *(const float2*)&Wrbf[b * HID + c];
    }

    // phase-B irrep indices for this thread's 5 spherical slots
    int irA[5];
#pragma unroll
    for (int r = 0; r < 5; r++) {
        int j = t + 96 * r;
        irA[r] = (j < 128) ? j
                           : ((j < 320) ? 128 + (j - 128) / 3
                                        : 192 + (j - 320) / 5);
    }

    __shared__ __align__(16) float s_fo[EB][HID];
    __shared__ __align__(16) float s_m[EB][SPH];
    __shared__ float s_rbf[EB][NB];
    __shared__ float s_fc[EB];
    __shared__ int s_src[EB], s_dst[EB];

    float* const out_sph = out + (size_t)NN * ND;
    const int nbatch = NE / EB;

    for (int batch = blockIdx.x; batch < nbatch; batch += gridDim.x) {
        const int e0 = batch * EB;

        // ---- stage per-batch scalars ----
        if (t < EB * NB) s_rbf[t / NB][t % NB] = rbf[e0 * NB + t];
        if (t >= 88 && t < 88 + EB) {
            int e = t - 88;
            s_fc[e] = fcut[e0 + e];
            s_dst[e] = eidx[e0 + e];
            s_src[e] = eidx[NE + e0 + e];
        }
        __syncthreads();

        // ---- phase A: filter matvec * fcut * scalar_out[src] ----
#pragma unroll
        for (int e = 0; e < EB; e++) {
            const float* soRow = g_so + (size_t)s_src[e] * HID;
            float2 so[3];
#pragma unroll
            for (int k = 0; k < 3; k++)
                so[k] = *(const float2*)&soRow[2 * (t + 96 * k)];

            float2 acc[3] = {bb2[0], bb2[1], bb2[2]};
#pragma unroll
            for (int b = 0; b < NB; b++) {
                float r = s_rbf[e][b];
                float2 r2 = make_float2(r, r);
                acc[0] = ffma2(r2, w2[0][b], acc[0]);
                acc[1] = ffma2(r2, w2[1][b], acc[1]);
                acc[2] = ffma2(r2, w2[2][b], acc[2]);
            }
            const float fc = s_fc[e];
#pragma unroll
            for (int k = 0; k < 3; k++) {
                float2 v;
                v.x = acc[k].x * fc * so[k].x;
                v.y = acc[k].y * fc * so[k].y;
                *(float2*)&s_fo[e][2 * (t + 96 * k)] = v;
            }
        }
        __syncthreads();

        // ---- phase B: gated spherical messages ----
#pragma unroll
        for (int e = 0; e < EB; e++) {
            const float* xr = xsph + (size_t)s_src[e] * SPH;
            const float* rr = rsh + (size_t)(e0 + e) * SPH;
#pragma unroll
            for (int r = 0; r < 5; r++) {
                int j = t + 96 * r;
                int ir = irA[r];
                s_m[e][j] = xr[j] * s_fo[e][ir] + rr[j] * s_fo[e][NIR + ir];
            }
        }
        __syncthreads();

        // ---- phase C: vectorized scatter-add ----
#pragma unroll
        for (int e = 0; e < EB; e++) {
            const int dst = s_dst[e];
            float* ob = out + (size_t)dst * ND;
            float* osb = out_sph + (size_t)dst * SPH;
            for (int q = t; q < 152; q += 96) {
                if (q < 32)
                    red4(ob + 4 * q, *(const float4*)&s_fo[e][2 * NIR + 4 * q]);
                else {
                    int s = q - 32;
                    red4(osb + 4 * s, *(const float4*)&s_m[e][4 * s]);
                }
            }
        }
        __syncthreads();   // protect s_fo/s_m (LDS feeding reds) before reuse
    }
}

// ---------------- launch ----------------
extern "C" void kernel_launch(void* const* d_in, const int* in_sizes, int n_in,
                              void* d_out, int out_size) {
    const float* xs   = (const float*)d_in[0];
    const float* xsph = (const float*)d_in[1];
    const float* rbf  = (const float*)d_in[2];
    const float* fcut = (const float*)d_in[3];
    const float* rsh  = (const float*)d_in[4];
    const int*   eidx = (const int*)d_in[5];
    const float* W1   = (const float*)d_in[6];
    const float* b1   = (const float*)d_in[7];
    const float* W2   = (const float*)d_in[8];
    const float* b2   = (const float*)d_in[9];
    const float* Wrbf = (const float*)d_in[10];
    const float* brbf = (const float*)d_in[11];
    float* out = (float*)d_out;

    float *ph, *pso;
    cudaGetSymbolAddress((void**)&ph, g_h);
    cudaGetSymbolAddress((void**)&pso, g_so);

    const int smem_bytes = (128 * 68 + 128 * 64) * 4;
    cudaFuncSetAttribute(gemm_k128<ND, true>,
                         cudaFuncAttributeMaxDynamicSharedMemorySize, smem_bytes);
    cudaFuncSetAttribute(gemm_k128<HID, false>,
                         cudaFuncAttributeMaxDynamicSharedMemorySize, smem_bytes);

    init_out_kernel<<<2048, 256>>>(xs, xsph, out);

    const int gblocks = (NN + 63) / 64;
    gemm_k128<ND, true><<<gblocks, 256, smem_bytes>>>(xs, W1, b1, ph, NN);
    gemm_k128<HID, false><<<gblocks, 256, smem_bytes>>>(ph, W2, b2, pso, NN);

    edge_kernel<<<444, 96>>>(xsph, rbf, fcut, rsh, eidx, Wrbf, brbf, out);
}